// round 15
// baseline (speedup 1.0000x reference)
#include <cuda_runtime.h>
#include <cuda_fp16.h>
#include <cstdint>

#define BZ 32
#define CH 64
#define HH 128
#define WW 128
#define RROWS 8          // output rows per CTA (2 per iteration, 4 iterations)
#define HW (HH * WW)
#define MPW 136          // words per c2-row of Mp: MPW%32==8 -> GEMM reads conflict-free
#define MPSLOT (32 * MPW)        // 4352 words per row-slot
#define WP_STRIDE 33     // words per o-row of packed weights (aliased into ring)
#define ZSL 68           // words per o-row of a z slot (64 px-pairs + 4 pad)
#define RINGSLOT (64 * ZSL)      // 4352 words per z row-slot

// dynamic smem layout (bytes):
//   Mp    uint32_t[4][32*136] @ 0       (69632)  fp16x2 3x3-presummed x rows (2 bufs x 2 rows)
//   ring  uint32_t[2][64*68]  @ 69632   (34816)  fp16x2 z rows (same-iteration produce/consume)
//         (Wp aliases ring start during phase 0 only)
//   BiasS float[64]           @ 104448  (256)
#define SMEM_BYTES 104704

static __device__ __forceinline__ float2 h2f(uint32_t w) {
    return __half22float2(*reinterpret_cast<__half2*>(&w));
}
static __device__ __forceinline__ uint32_t hadd2u(uint32_t a, uint32_t b) {
    __half2 r = __hadd2(*reinterpret_cast<__half2*>(&a), *reinterpret_cast<__half2*>(&b));
    return *reinterpret_cast<uint32_t*>(&r);
}
// convert one row's float4 pair-loads (2 groups x 2 channels) to 8 fp16x2 words
static __device__ __forceinline__ void cvt_row(const float4* xa, const float4* xc, uint32_t* c) {
    #pragma unroll
    for (int g = 0; g < 2; g++) {
        __half2 p0 = __floats2half2_rn(xa[g].x, xc[g].x);
        __half2 p1 = __floats2half2_rn(xa[g].y, xc[g].y);
        __half2 p2 = __floats2half2_rn(xa[g].z, xc[g].z);
        __half2 p3 = __floats2half2_rn(xa[g].w, xc[g].w);
        c[4 * g + 0] = *reinterpret_cast<uint32_t*>(&p0);
        c[4 * g + 1] = *reinterpret_cast<uint32_t*>(&p1);
        c[4 * g + 2] = *reinterpret_cast<uint32_t*>(&p2);
        c[4 * g + 3] = *reinterpret_cast<uint32_t*>(&p3);
    }
}
// horizontal edge-clipped 3-sum of one converted row (word == pixel).
// Thread (lane&15)=l holds px {4l..4l+3} (g0) and {64+4l..64+4l+3} (g1);
// boundary words come from half-warp neighbor lanes (image edges clip to 0).
static __device__ __forceinline__ void hsum_row(const uint32_t* c, uint32_t* h, int lane) {
    const int hl   = lane & 15;
    const int lidx = (lane & 16) | ((lane - 1) & 15);
    const int ridx = (lane & 16) | ((lane + 1) & 15);
    const uint32_t sl3 = __shfl_sync(0xffffffffu, c[3], lidx);
    const uint32_t sl7 = __shfl_sync(0xffffffffu, c[7], lidx);
    const uint32_t sr0 = __shfl_sync(0xffffffffu, c[0], ridx);
    const uint32_t sr4 = __shfl_sync(0xffffffffu, c[4], ridx);
    const uint32_t Lw0 = (hl == 0)  ? 0u  : sl3;   // px 4l-1   (edge: p=-1)
    const uint32_t Lw1 = (hl == 0)  ? sl3 : sl7;   // px 63+4l  (l=0: lane15 g0w3)
    const uint32_t Rw0 = (hl == 15) ? sr4 : sr0;   // px 4l+4   (l=15: lane0 g1w0)
    const uint32_t Rw1 = (hl == 15) ? 0u  : sr4;   // px 68+4l  (edge: p=128)
    h[0] = hadd2u(hadd2u(Lw0,  c[0]), c[1]);
    h[1] = hadd2u(hadd2u(c[0], c[1]), c[2]);
    h[2] = hadd2u(hadd2u(c[1], c[2]), c[3]);
    h[3] = hadd2u(hadd2u(c[2], c[3]), Rw0);
    h[4] = hadd2u(hadd2u(Lw1,  c[4]), c[5]);
    h[5] = hadd2u(hadd2u(c[4], c[5]), c[6]);
    h[6] = hadd2u(hadd2u(c[5], c[6]), c[7]);
    h[7] = hadd2u(hadd2u(c[6], c[7]), Rw1);
}

__global__ __launch_bounds__(512, 1)
void denoise_fused(const float* __restrict__ x,
                   const float* __restrict__ conv_w,
                   const float* __restrict__ conv_b,
                   float* __restrict__ out) {
    extern __shared__ unsigned char smraw[];
    uint32_t* Mp    = reinterpret_cast<uint32_t*>(smraw);
    uint32_t* ring  = reinterpret_cast<uint32_t*>(smraw + 69632);
    uint32_t* Wp    = ring;                       // alias, consumed before ring use
    float*    BiasS = reinterpret_cast<float*>(smraw + 104448);

    const int tid  = threadIdx.x;
    const int warp = tid >> 5;
    const int lane = tid & 31;

    const int b  = blockIdx.y;
    const int h0 = blockIdx.x * RROWS;

    // ---------- phase 0: stage weights fp16x2 + bias ----------
    for (int i = tid; i < 64 * 32; i += 512) {
        const int o = i >> 5, c2 = i & 31;
        const float2 wv = reinterpret_cast<const float2*>(conv_w)[o * 32 + c2];
        __half2 pk = __floats2half2_rn(wv.x, wv.y);
        Wp[o * WP_STRIDE + c2] = *reinterpret_cast<uint32_t*>(&pk);
    }
    if (tid < 64) BiasS[tid] = conv_b[tid];
    __syncthreads();

    // GEMM tiling: warps 0-7 -> row 0 of pair, 8-15 -> row 1.
    // Within 8 warps: 2 M-groups x 4 N-slices; 2 MMAs per B-fragment load.
    const int wrow = warp >> 3;
    const int wr   = warp & 7;
    const int o0   = (wr & 1) * 32;
    const int nsub = (wr >> 1) * 32;
    const int lq = lane >> 2;   // 0..7
    const int lr = lane & 3;    // 0..3

    uint32_t a[2][4][4];
    #pragma unroll
    for (int mt = 0; mt < 2; mt++) {
        const int ot = o0 + mt * 16;
        #pragma unroll
        for (int kk = 0; kk < 4; kk++) {
            a[mt][kk][0] = Wp[(ot + lq)     * WP_STRIDE + kk * 8 + lr];
            a[mt][kk][1] = Wp[(ot + 8 + lq) * WP_STRIDE + kk * 8 + lr];
            a[mt][kk][2] = Wp[(ot + lq)     * WP_STRIDE + kk * 8 + 4 + lr];
            a[mt][kk][3] = Wp[(ot + 8 + lq) * WP_STRIDE + kk * 8 + 4 + lr];
        }
    }

    const float* xb = x   + (size_t)b * CH * HW;
    float*       ob = out + (size_t)b * CH * HW;

    // per-thread load coords: channel pair c2p, two 4-px groups (pxp, pxp+64)
    const int c2p = tid >> 4;           // 0..31
    const int pxp = (tid & 15) * 4;     // 0..60
    const float* base0 = xb + (size_t)(2 * c2p)     * HW;
    const float* base1 = xb + (size_t)(2 * c2p + 1) * HW;

    // ---------- prologue: rolling vertical window over h-summed rows ----------
    uint32_t xprev[8], sprev[8];
    {
        uint32_t xm1[8] = {0u,0u,0u,0u,0u,0u,0u,0u};
        float4 la[2], lc[2];
        if (h0 > 0) {
            #pragma unroll
            for (int g = 0; g < 2; g++) {
                la[g] = *reinterpret_cast<const float4*>(base0 + (h0 - 1) * WW + pxp + 64 * g);
                lc[g] = *reinterpret_cast<const float4*>(base1 + (h0 - 1) * WW + pxp + 64 * g);
            }
            cvt_row(la, lc, xm1);
        }
        uint32_t hm1[8];
        hsum_row(xm1, hm1, lane);
        #pragma unroll
        for (int g = 0; g < 2; g++) {
            la[g] = *reinterpret_cast<const float4*>(base0 + h0 * WW + pxp + 64 * g);
            lc[g] = *reinterpret_cast<const float4*>(base1 + h0 * WW + pxp + 64 * g);
        }
        uint32_t x0[8], h0r[8];
        cvt_row(la, lc, x0);
        hsum_row(x0, h0r, lane);
        #pragma unroll
        for (int j = 0; j < 8; j++) {
            sprev[j] = hadd2u(hm1[j], h0r[j]);
            xprev[j] = h0r[j];
        }
    }
    // prefetch rows h0+1, h0+2 (always in-bounds: h0 <= 120)
    float4 pa[2][2], pc[2][2];
    #pragma unroll
    for (int k = 0; k < 2; k++) {
        const int rr = h0 + 1 + k;
        #pragma unroll
        for (int g = 0; g < 2; g++) {
            pa[k][g] = *reinterpret_cast<const float4*>(base0 + rr * WW + pxp + 64 * g);
            pc[k][g] = *reinterpret_cast<const float4*>(base1 + rr * WW + pxp + 64 * g);
        }
    }

    // ---------- pipeline: 4 iterations, 2 output rows each ----------
    #pragma unroll 1
    for (int i = 0; i < 4; i++) {
        const int ro0 = h0 + 2 * i;
        uint32_t* mpb = Mp + (i & 1) * (2 * MPSLOT);

        // convert + h-sum incoming rows ro0+1 (always valid), ro0+2 (guard)
        {
            uint32_t c1[8], c2r[8] = {0u,0u,0u,0u,0u,0u,0u,0u};
            cvt_row(pa[0], pc[0], c1);
            if (ro0 + 2 < HH) cvt_row(pa[1], pc[1], c2r);
            uint32_t h1[8], h2[8];
            hsum_row(c1,  h1, lane);
            hsum_row(c2r, h2, lane);

            // vertical 3-sums of h-rows -> Mp (full 3x3 sums, fp16x2)
            uint32_t xv0[8], xv1[8];
            #pragma unroll
            for (int j = 0; j < 8; j++) {
                xv0[j] = hadd2u(sprev[j], h1[j]);
                xv1[j] = hadd2u(hadd2u(xprev[j], h1[j]), h2[j]);
                sprev[j] = hadd2u(h1[j], h2[j]);
                xprev[j] = h2[j];
            }
            #pragma unroll
            for (int g = 0; g < 2; g++) {
                *reinterpret_cast<uint4*>(&mpb[c2p * MPW + pxp + 64 * g]) =
                    *reinterpret_cast<uint4*>(&xv0[4 * g]);
                *reinterpret_cast<uint4*>(&mpb[MPSLOT + c2p * MPW + pxp + 64 * g]) =
                    *reinterpret_cast<uint4*>(&xv1[4 * g]);
            }
        }

        // issue epilogue x loads NOW (hidden behind the GEMM phase)
        float4 ex0[4], ex1[4];
        #pragma unroll
        for (int it = 0; it < 4; it++) {
            const int idx  = it * 512 + tid;
            const int o    = idx >> 5;
            const int rowk = (idx >> 4) & 1;
            const int q4   = idx & 15;
            const size_t off = (size_t)o * HW + (ro0 + rowk) * WW + q4 * 8;
            ex0[it] = __ldcs(reinterpret_cast<const float4*>(xb + off));
            ex1[it] = __ldcs(reinterpret_cast<const float4*>(xb + off + 4));
        }
        __syncthreads();   // Mp pair ready; ring slots free (prev epilogue done)

        // -- GEMM: z[o,p] = sum_c W[o,c] * s3x3[c,p] for row pair --
        {
            const uint32_t* mp = mpb + wrow * MPSLOT;
            uint32_t* zs = ring + wrow * RINGSLOT;
            #pragma unroll
            for (int nt = 0; nt < 4; nt++) {
                const int n0 = nsub + nt * 8;
                float ac[2][4];
                #pragma unroll
                for (int mt = 0; mt < 2; mt++)
                    ac[mt][0] = ac[mt][1] = ac[mt][2] = ac[mt][3] = 0.f;
                #pragma unroll
                for (int kk = 0; kk < 4; kk++) {
                    const uint32_t b0 = mp[(kk * 8 + lr)     * MPW + n0 + lq];
                    const uint32_t b1 = mp[(kk * 8 + 4 + lr) * MPW + n0 + lq];
                    #pragma unroll
                    for (int mt = 0; mt < 2; mt++) {
                        asm volatile(
                            "mma.sync.aligned.m16n8k16.row.col.f32.f16.f16.f32 "
                            "{%0,%1,%2,%3}, {%4,%5,%6,%7}, {%8,%9}, {%0,%1,%2,%3};\n"
                            : "+f"(ac[mt][0]), "+f"(ac[mt][1]),
                              "+f"(ac[mt][2]), "+f"(ac[mt][3])
                            : "r"(a[mt][kk][0]), "r"(a[mt][kk][1]),
                              "r"(a[mt][kk][2]), "r"(a[mt][kk][3]),
                              "r"(b0), "r"(b1));
                    }
                }
                #pragma unroll
                for (int mt = 0; mt < 2; mt++) {
                    const int oA = o0 + mt * 16 + lq;
                    __half2 d01 = __floats2half2_rn(ac[mt][0], ac[mt][1]);
                    __half2 d23 = __floats2half2_rn(ac[mt][2], ac[mt][3]);
                    zs[oA       * ZSL + (n0 >> 1) + lr] = *reinterpret_cast<uint32_t*>(&d01);
                    zs[(oA + 8) * ZSL + (n0 >> 1) + lr] = *reinterpret_cast<uint32_t*>(&d23);
                }
            }
        }

        // prefetch rows ro0+3, ro0+4 (hidden behind epilogue + next commit)
        if (i < 3) {
            #pragma unroll
            for (int k = 0; k < 2; k++) {
                const int rr = ro0 + 3 + k;
                if (rr < HH) {
                    #pragma unroll
                    for (int g = 0; g < 2; g++) {
                        pa[k][g] = *reinterpret_cast<const float4*>(base0 + rr * WW + pxp + 64 * g);
                        pc[k][g] = *reinterpret_cast<const float4*>(base1 + rr * WW + pxp + 64 * g);
                    }
                }
            }
        }
        __syncthreads();   // z pair ready

        // -- epilogue: scale + residual + bias (z is the full 3x3 sum) --
        #pragma unroll
        for (int it = 0; it < 4; it++) {
            const int idx  = it * 512 + tid;
            const int o    = idx >> 5;          // out channel 0..63
            const int rowk = (idx >> 4) & 1;
            const int q4   = idx & 15;          // uint4 group (8 px)
            const int ro   = ro0 + rowk;

            const uint32_t* zv = ring + rowk * RINGSLOT;
            const uint4 m4 = *reinterpret_cast<const uint4*>(&zv[o * ZSL + q4 * 4]);
            float v[8];
            {
                float2 m;
                m = h2f(m4.x); v[0] = m.x; v[1] = m.y;
                m = h2f(m4.y); v[2] = m.x; v[3] = m.y;
                m = h2f(m4.z); v[4] = m.x; v[5] = m.y;
                m = h2f(m4.w); v[6] = m.x; v[7] = m.y;
            }
            const float invh = (ro == 0 || ro == HH - 1) ? 0.5f : (1.0f / 3.0f);
            const float iw  = (1.0f / 3.0f) * invh;
            const float iwL = (q4 == 0)  ? 0.5f * invh : iw;
            const float iwR = (q4 == 15) ? 0.5f * invh : iw;
            const float bo = BiasS[o];
            const size_t off = (size_t)o * HW + ro * WW + q4 * 8;

            float4 o0v, o1v;
            o0v.x = ex0[it].x + bo + v[0] * iwL;
            o0v.y = ex0[it].y + bo + v[1] * iw;
            o0v.z = ex0[it].z + bo + v[2] * iw;
            o0v.w = ex0[it].w + bo + v[3] * iw;
            o1v.x = ex1[it].x + bo + v[4] * iw;
            o1v.y = ex1[it].y + bo + v[5] * iw;
            o1v.z = ex1[it].z + bo + v[6] * iw;
            o1v.w = ex1[it].w + bo + v[7] * iwR;
            __stcs(reinterpret_cast<float4*>(ob + off), o0v);
            __stcs(reinterpret_cast<float4*>(ob + off + 4), o1v);
        }
        // next iteration's first barrier fences ring reuse
    }
}

extern "C" void kernel_launch(void* const* d_in, const int* in_sizes, int n_in,
                              void* d_out, int out_size) {
    const float* x      = (const float*)d_in[0];
    const float* conv_w = (const float*)d_in[1];
    const float* conv_b = (const float*)d_in[2];
    float* out = (float*)d_out;

    cudaFuncSetAttribute(denoise_fused,
                         cudaFuncAttributeMaxDynamicSharedMemorySize, SMEM_BYTES);
    dim3 grid(HH / RROWS, BZ);               // 16 x 32 = 512 CTAs
    denoise_fused<<<grid, 512, SMEM_BYTES>>>(x, conv_w, conv_b, out);
}

// round 16
// speedup vs baseline: 1.1924x; 1.1924x over previous
#include <cuda_runtime.h>
#include <cuda_fp16.h>
#include <cstdint>

#define BZ 32
#define CH 64
#define HH 128
#define WW 128
#define RROWS 8          // output rows per CTA (2 per iteration, 4 iterations)
#define HW (HH * WW)
#define MPW 136          // words per c2-row of Mp: MPW%32==8 -> GEMM reads conflict-free
#define MPSLOT (32 * MPW)        // 4352 words per row-slot
#define WP_STRIDE 33     // words per o-row of packed weights (aliased into ring)
#define ZSL 68           // words per o-row of a z slot (64 px-pairs + 4 pad)
#define RINGSLOT (64 * ZSL)      // 4352 words per z row-slot

// dynamic smem layout (bytes):
//   Mp    uint32_t[4][32*136] @ 0       (69632)  fp16x2 3x3-presummed x rows (2 bufs x 2 rows)
//   ring  uint32_t[2][64*68]  @ 69632   (34816)  fp16x2 z rows (same-iteration produce/consume)
//         (Wp aliases ring start during phase 0 only)
//   BiasS float[64]           @ 104448  (256)
#define SMEM_BYTES 104704

static __device__ __forceinline__ float2 h2f(uint32_t w) {
    return __half22float2(*reinterpret_cast<__half2*>(&w));
}
static __device__ __forceinline__ uint32_t hadd2u(uint32_t a, uint32_t b) {
    __half2 r = __hadd2(*reinterpret_cast<__half2*>(&a), *reinterpret_cast<__half2*>(&b));
    return *reinterpret_cast<uint32_t*>(&r);
}
// convert one row's float4 pair-loads (2 groups x 2 channels) to 8 fp16x2 words
static __device__ __forceinline__ void cvt_row(const float4* xa, const float4* xc, uint32_t* c) {
    #pragma unroll
    for (int g = 0; g < 2; g++) {
        __half2 p0 = __floats2half2_rn(xa[g].x, xc[g].x);
        __half2 p1 = __floats2half2_rn(xa[g].y, xc[g].y);
        __half2 p2 = __floats2half2_rn(xa[g].z, xc[g].z);
        __half2 p3 = __floats2half2_rn(xa[g].w, xc[g].w);
        c[4 * g + 0] = *reinterpret_cast<uint32_t*>(&p0);
        c[4 * g + 1] = *reinterpret_cast<uint32_t*>(&p1);
        c[4 * g + 2] = *reinterpret_cast<uint32_t*>(&p2);
        c[4 * g + 3] = *reinterpret_cast<uint32_t*>(&p3);
    }
}
// horizontal edge-clipped 3-sum of one converted row (word == pixel).
// Thread (lane&15)=l holds px {4l..4l+3} (g0) and {64+4l..64+4l+3} (g1);
// boundary words come from half-warp neighbor lanes (image edges clip to 0).
static __device__ __forceinline__ void hsum_row(const uint32_t* c, uint32_t* h, int lane) {
    const int hl   = lane & 15;
    const int lidx = (lane & 16) | ((lane - 1) & 15);
    const int ridx = (lane & 16) | ((lane + 1) & 15);
    const uint32_t sl3 = __shfl_sync(0xffffffffu, c[3], lidx);
    const uint32_t sl7 = __shfl_sync(0xffffffffu, c[7], lidx);
    const uint32_t sr0 = __shfl_sync(0xffffffffu, c[0], ridx);
    const uint32_t sr4 = __shfl_sync(0xffffffffu, c[4], ridx);
    const uint32_t Lw0 = (hl == 0)  ? 0u  : sl3;   // px 4l-1   (edge: p=-1)
    const uint32_t Lw1 = (hl == 0)  ? sl3 : sl7;   // px 63+4l  (l=0: lane15 g0w3)
    const uint32_t Rw0 = (hl == 15) ? sr4 : sr0;   // px 4l+4   (l=15: lane0 g1w0)
    const uint32_t Rw1 = (hl == 15) ? 0u  : sr4;   // px 68+4l  (edge: p=128)
    h[0] = hadd2u(hadd2u(Lw0,  c[0]), c[1]);
    h[1] = hadd2u(hadd2u(c[0], c[1]), c[2]);
    h[2] = hadd2u(hadd2u(c[1], c[2]), c[3]);
    h[3] = hadd2u(hadd2u(c[2], c[3]), Rw0);
    h[4] = hadd2u(hadd2u(Lw1,  c[4]), c[5]);
    h[5] = hadd2u(hadd2u(c[4], c[5]), c[6]);
    h[6] = hadd2u(hadd2u(c[5], c[6]), c[7]);
    h[7] = hadd2u(hadd2u(c[6], c[7]), Rw1);
}

__global__ __launch_bounds__(512, 1)
void denoise_fused(const float* __restrict__ x,
                   const float* __restrict__ conv_w,
                   const float* __restrict__ conv_b,
                   float* __restrict__ out) {
    extern __shared__ unsigned char smraw[];
    uint32_t* Mp    = reinterpret_cast<uint32_t*>(smraw);
    uint32_t* ring  = reinterpret_cast<uint32_t*>(smraw + 69632);
    uint32_t* Wp    = ring;                       // alias, consumed before ring use
    float*    BiasS = reinterpret_cast<float*>(smraw + 104448);

    const int tid  = threadIdx.x;
    const int warp = tid >> 5;
    const int lane = tid & 31;

    const int b  = blockIdx.y;
    const int h0 = blockIdx.x * RROWS;

    // ---------- phase 0: stage weights fp16x2 + bias ----------
    for (int i = tid; i < 64 * 32; i += 512) {
        const int o = i >> 5, c2 = i & 31;
        const float2 wv = reinterpret_cast<const float2*>(conv_w)[o * 32 + c2];
        __half2 pk = __floats2half2_rn(wv.x, wv.y);
        Wp[o * WP_STRIDE + c2] = *reinterpret_cast<uint32_t*>(&pk);
    }
    if (tid < 64) BiasS[tid] = conv_b[tid];
    __syncthreads();

    // GEMM tiling: warps 0-7 -> row 0 of pair, 8-15 -> row 1.
    // Within 8 warps: 2 M-groups x 4 N-slices; 2 MMAs per B-fragment load.
    const int wrow = warp >> 3;
    const int wr   = warp & 7;
    const int o0   = (wr & 1) * 32;
    const int nsub = (wr >> 1) * 32;
    const int lq = lane >> 2;   // 0..7
    const int lr = lane & 3;    // 0..3

    uint32_t a[2][4][4];
    #pragma unroll
    for (int mt = 0; mt < 2; mt++) {
        const int ot = o0 + mt * 16;
        #pragma unroll
        for (int kk = 0; kk < 4; kk++) {
            a[mt][kk][0] = Wp[(ot + lq)     * WP_STRIDE + kk * 8 + lr];
            a[mt][kk][1] = Wp[(ot + 8 + lq) * WP_STRIDE + kk * 8 + lr];
            a[mt][kk][2] = Wp[(ot + lq)     * WP_STRIDE + kk * 8 + 4 + lr];
            a[mt][kk][3] = Wp[(ot + 8 + lq) * WP_STRIDE + kk * 8 + 4 + lr];
        }
    }

    const float* xb = x   + (size_t)b * CH * HW;
    float*       ob = out + (size_t)b * CH * HW;

    // per-thread load coords: channel pair c2p, two 4-px groups (pxp, pxp+64)
    const int c2p = tid >> 4;           // 0..31
    const int pxp = (tid & 15) * 4;     // 0..60
    const float* base0 = xb + (size_t)(2 * c2p)     * HW;
    const float* base1 = xb + (size_t)(2 * c2p + 1) * HW;

    // ---------- prologue: rolling vertical window over h-summed rows ----------
    uint32_t xprev[8], sprev[8];
    {
        uint32_t xm1[8] = {0u,0u,0u,0u,0u,0u,0u,0u};
        float4 la[2], lc[2];
        if (h0 > 0) {
            #pragma unroll
            for (int g = 0; g < 2; g++) {
                la[g] = *reinterpret_cast<const float4*>(base0 + (h0 - 1) * WW + pxp + 64 * g);
                lc[g] = *reinterpret_cast<const float4*>(base1 + (h0 - 1) * WW + pxp + 64 * g);
            }
            cvt_row(la, lc, xm1);
        }
        uint32_t hm1[8];
        hsum_row(xm1, hm1, lane);
        #pragma unroll
        for (int g = 0; g < 2; g++) {
            la[g] = *reinterpret_cast<const float4*>(base0 + h0 * WW + pxp + 64 * g);
            lc[g] = *reinterpret_cast<const float4*>(base1 + h0 * WW + pxp + 64 * g);
        }
        uint32_t x0[8], h0r[8];
        cvt_row(la, lc, x0);
        hsum_row(x0, h0r, lane);
        #pragma unroll
        for (int j = 0; j < 8; j++) {
            sprev[j] = hadd2u(hm1[j], h0r[j]);
            xprev[j] = h0r[j];
        }
    }
    // prefetch rows h0+1, h0+2 (always in-bounds: h0 <= 120)
    float4 pa[2][2], pc[2][2];
    #pragma unroll
    for (int k = 0; k < 2; k++) {
        const int rr = h0 + 1 + k;
        #pragma unroll
        for (int g = 0; g < 2; g++) {
            pa[k][g] = *reinterpret_cast<const float4*>(base0 + rr * WW + pxp + 64 * g);
            pc[k][g] = *reinterpret_cast<const float4*>(base1 + rr * WW + pxp + 64 * g);
        }
    }

    // ---------- pipeline: 4 iterations, 2 output rows each ----------
    #pragma unroll 1
    for (int i = 0; i < 4; i++) {
        const int ro0 = h0 + 2 * i;
        uint32_t* mpb = Mp + (i & 1) * (2 * MPSLOT);

        // convert + h-sum incoming rows ro0+1 (always valid), ro0+2 (guard)
        {
            uint32_t c1[8], c2r[8] = {0u,0u,0u,0u,0u,0u,0u,0u};
            cvt_row(pa[0], pc[0], c1);
            if (ro0 + 2 < HH) cvt_row(pa[1], pc[1], c2r);
            uint32_t h1[8], h2[8];
            hsum_row(c1,  h1, lane);
            hsum_row(c2r, h2, lane);

            // vertical 3-sums of h-rows -> Mp (full 3x3 sums, fp16x2)
            uint32_t xv0[8], xv1[8];
            #pragma unroll
            for (int j = 0; j < 8; j++) {
                xv0[j] = hadd2u(sprev[j], h1[j]);
                xv1[j] = hadd2u(hadd2u(xprev[j], h1[j]), h2[j]);
                sprev[j] = hadd2u(h1[j], h2[j]);
                xprev[j] = h2[j];
            }
            #pragma unroll
            for (int g = 0; g < 2; g++) {
                *reinterpret_cast<uint4*>(&mpb[c2p * MPW + pxp + 64 * g]) =
                    *reinterpret_cast<uint4*>(&xv0[4 * g]);
                *reinterpret_cast<uint4*>(&mpb[MPSLOT + c2p * MPW + pxp + 64 * g]) =
                    *reinterpret_cast<uint4*>(&xv1[4 * g]);
            }
        }

        // prefetch rows ro0+3, ro0+4 for next iteration (guard < HH)
        if (i < 3) {
            #pragma unroll
            for (int k = 0; k < 2; k++) {
                const int rr = ro0 + 3 + k;
                if (rr < HH) {
                    #pragma unroll
                    for (int g = 0; g < 2; g++) {
                        pa[k][g] = *reinterpret_cast<const float4*>(base0 + rr * WW + pxp + 64 * g);
                        pc[k][g] = *reinterpret_cast<const float4*>(base1 + rr * WW + pxp + 64 * g);
                    }
                }
            }
        }
        __syncthreads();   // Mp pair ready; ring slots free (prev epilogue done)

        // -- GEMM: z[o,p] = sum_c W[o,c] * s3x3[c,p] for row pair --
        {
            const uint32_t* mp = mpb + wrow * MPSLOT;
            uint32_t* zs = ring + wrow * RINGSLOT;
            #pragma unroll
            for (int nt = 0; nt < 4; nt++) {
                const int n0 = nsub + nt * 8;
                float ac[2][4];
                #pragma unroll
                for (int mt = 0; mt < 2; mt++)
                    ac[mt][0] = ac[mt][1] = ac[mt][2] = ac[mt][3] = 0.f;
                #pragma unroll
                for (int kk = 0; kk < 4; kk++) {
                    const uint32_t b0 = mp[(kk * 8 + lr)     * MPW + n0 + lq];
                    const uint32_t b1 = mp[(kk * 8 + 4 + lr) * MPW + n0 + lq];
                    #pragma unroll
                    for (int mt = 0; mt < 2; mt++) {
                        asm volatile(
                            "mma.sync.aligned.m16n8k16.row.col.f32.f16.f16.f32 "
                            "{%0,%1,%2,%3}, {%4,%5,%6,%7}, {%8,%9}, {%0,%1,%2,%3};\n"
                            : "+f"(ac[mt][0]), "+f"(ac[mt][1]),
                              "+f"(ac[mt][2]), "+f"(ac[mt][3])
                            : "r"(a[mt][kk][0]), "r"(a[mt][kk][1]),
                              "r"(a[mt][kk][2]), "r"(a[mt][kk][3]),
                              "r"(b0), "r"(b1));
                    }
                }
                #pragma unroll
                for (int mt = 0; mt < 2; mt++) {
                    const int oA = o0 + mt * 16 + lq;
                    __half2 d01 = __floats2half2_rn(ac[mt][0], ac[mt][1]);
                    __half2 d23 = __floats2half2_rn(ac[mt][2], ac[mt][3]);
                    zs[oA       * ZSL + (n0 >> 1) + lr] = *reinterpret_cast<uint32_t*>(&d01);
                    zs[(oA + 8) * ZSL + (n0 >> 1) + lr] = *reinterpret_cast<uint32_t*>(&d23);
                }
            }
        }
        __syncthreads();   // z pair ready

        // -- epilogue: scale + residual + bias (z is the full 3x3 sum) --
        #pragma unroll
        for (int it = 0; it < 4; it++) {
            const int idx  = it * 512 + tid;
            const int o    = idx >> 5;          // out channel 0..63
            const int rowk = (idx >> 4) & 1;
            const int q4   = idx & 15;          // uint4 group (8 px)
            const int ro   = ro0 + rowk;

            const uint32_t* zv = ring + rowk * RINGSLOT;
            const uint4 m4 = *reinterpret_cast<const uint4*>(&zv[o * ZSL + q4 * 4]);
            float v[8];
            {
                float2 m;
                m = h2f(m4.x); v[0] = m.x; v[1] = m.y;
                m = h2f(m4.y); v[2] = m.x; v[3] = m.y;
                m = h2f(m4.z); v[4] = m.x; v[5] = m.y;
                m = h2f(m4.w); v[6] = m.x; v[7] = m.y;
            }
            const float invh = (ro == 0 || ro == HH - 1) ? 0.5f : (1.0f / 3.0f);
            const float iw  = (1.0f / 3.0f) * invh;
            const float iwL = (q4 == 0)  ? 0.5f * invh : iw;
            const float iwR = (q4 == 15) ? 0.5f * invh : iw;
            const float bo = BiasS[o];
            const size_t off = (size_t)o * HW + ro * WW + q4 * 8;

            const float4 x0 = __ldcs(reinterpret_cast<const float4*>(xb + off));
            const float4 x1 = __ldcs(reinterpret_cast<const float4*>(xb + off + 4));
            float4 o0v, o1v;
            o0v.x = x0.x + bo + v[0] * iwL;
            o0v.y = x0.y + bo + v[1] * iw;
            o0v.z = x0.z + bo + v[2] * iw;
            o0v.w = x0.w + bo + v[3] * iw;
            o1v.x = x1.x + bo + v[4] * iw;
            o1v.y = x1.y + bo + v[5] * iw;
            o1v.z = x1.z + bo + v[6] * iw;
            o1v.w = x1.w + bo + v[7] * iwR;
            __stcs(reinterpret_cast<float4*>(ob + off), o0v);
            __stcs(reinterpret_cast<float4*>(ob + off + 4), o1v);
        }
        // next iteration's first barrier fences ring reuse
    }
}

extern "C" void kernel_launch(void* const* d_in, const int* in_sizes, int n_in,
                              void* d_out, int out_size) {
    const float* x      = (const float*)d_in[0];
    const float* conv_w = (const float*)d_in[1];
    const float* conv_b = (const float*)d_in[2];
    float* out = (float*)d_out;

    cudaFuncSetAttribute(denoise_fused,
                         cudaFuncAttributeMaxDynamicSharedMemorySize, SMEM_BYTES);
    dim3 grid(HH / RROWS, BZ);               // 16 x 32 = 512 CTAs
    denoise_fused<<<grid, 512, SMEM_BYTES>>>(x, conv_w, conv_b, out);
}